// round 15
// baseline (speedup 1.0000x reference)
#include <cuda_runtime.h>

#define H_IMG 512
#define W_IMG 512
#define NPLANES 96            // 32 * 3
#define TW 32
#define TH 32
#define IW 42                 // TW + 10
#define IH 42                 // TH + 10
#define SS2 43                // staged (g,r) float2 stride
#define MS2 33                // intermediate float2 stride
#define NT 256
#define NBX 16
#define NBY 16
#define NTILES (NBX * NBY * NPLANES)   // 24576
#define NPERS 740             // 148 SMs x 5 resident CTAs
#define C1F 6.5025f
#define C2F 58.5225f
#define NPIX 25165824.0       // 32*3*512*512

__device__ float g_partials[NPERS];
__device__ unsigned int g_count = 0;

#define W11_INIT {0.00102838f, 0.00759871f, 0.03600077f, 0.10936070f, \
                  0.21300560f, 0.26601180f, 0.21300560f, 0.10936070f, \
                  0.03600077f, 0.00759871f, 0.00102838f}

__global__ void __launch_bounds__(NT, 5) ssim_main(const float* __restrict__ gen,
                                                   const float* __restrict__ ref,
                                                   float* __restrict__ out) {
    __shared__ float2 sgr[IH * SS2];   // staged (g, r), scaled
    __shared__ float2 pm[IH * MS2];    // (conv_h g, conv_h r)
    __shared__ float2 pv[IH * MS2];    // (conv_h g^2+r^2, conv_h g*r)
    __shared__ float wsum[8];
    __shared__ double dsum[8];
    __shared__ bool is_last;

    const float W11[11] = W11_INIT;    // compile-time consts -> FFMA-imm

    const int tid = threadIdx.x;
    const int lane = tid & 31;
    const int wrp = tid >> 5;
    const int b = blockIdx.x;

    // contiguous tile range, y-innermost ordering: i -> (y = i&15, x, z)
    const int extra = (b < 156) ? b : 156;
    const int start = b * 33 + extra;
    const int end = start + 33 + (b < 156 ? 1 : 0);

    float lsum = 0.f;

    // stage nrows input rows starting at image row gy0 into sgr slots 0..nrows-1
#define STAGE(GY0, NROWS)                                                     \
    {                                                                         \
        const int gy0_ = (GY0);                                               \
        const int nr_ = (NROWS);                                              \
        if (xin && gy0_ >= 0 && gy0_ + nr_ <= H_IMG) {                        \
            const float* gb_ = gp + (long)gy0_ * W_IMG + (x0 - 5);            \
            const float* rb_ = rp + (long)gy0_ * W_IMG + (x0 - 5);            \
            for (int r_ = wrp; r_ < nr_; r_ += 8) {                           \
                const float* grow_ = gb_ + (long)r_ * W_IMG;                  \
                const float* rrow_ = rb_ + (long)r_ * W_IMG;                  \
                float2* srow_ = sgr + r_ * SS2;                               \
                srow_[lane] = make_float2(fmaf(grow_[lane], 0.5f, 0.5f),      \
                                          fmaf(rrow_[lane], 0.5f, 0.5f));     \
                if (lane < IW - 32)                                           \
                    srow_[lane + 32] =                                        \
                        make_float2(fmaf(grow_[lane + 32], 0.5f, 0.5f),       \
                                    fmaf(rrow_[lane + 32], 0.5f, 0.5f));      \
            }                                                                 \
        } else {                                                              \
            for (int r_ = wrp; r_ < nr_; r_ += 8) {                           \
                int gy_ = gy0_ + r_;                                          \
                bool rowok_ = (unsigned)gy_ < (unsigned)H_IMG;                \
                const float* grow_ = gp + (long)gy_ * W_IMG;                  \
                const float* rrow_ = rp + (long)gy_ * W_IMG;                  \
                float2* srow_ = sgr + r_ * SS2;                               \
                _Pragma("unroll")                                             \
                for (int h_ = 0; h_ < 2; h_++) {                              \
                    int c_ = lane + h_ * 32;                                  \
                    if (c_ < IW) {                                            \
                        int gx_ = x0 + c_ - 5;                                \
                        bool ok_ = rowok_ & ((unsigned)gx_ < (unsigned)W_IMG);\
                        srow_[c_] = ok_ ? make_float2(                        \
                                              fmaf(grow_[gx_], 0.5f, 0.5f),  \
                                              fmaf(rrow_[gx_], 0.5f, 0.5f))  \
                                        : make_float2(0.f, 0.f);              \
                    }                                                         \
                }                                                             \
            }                                                                 \
        }                                                                     \
    }

    // horizontal conv of one 4-col chunk: sgr slot SLOT -> pm/pv row OROW
#define HCONV(SLOT, OROW, C0)                                                 \
    {                                                                         \
        const float2* srow = sgr + (SLOT) * SS2 + (C0);                       \
        const int o = (OROW) * MS2 + (C0);                                    \
        float2 w[14];                                                         \
        _Pragma("unroll")                                                     \
        for (int t = 0; t < 14; t++) w[t] = srow[t];                          \
        {                                                                     \
            float s1[4] = {0.f, 0.f, 0.f, 0.f};                               \
            float s2[4] = {0.f, 0.f, 0.f, 0.f};                               \
            _Pragma("unroll")                                                 \
            for (int k = 0; k < 11; k++) {                                    \
                _Pragma("unroll")                                             \
                for (int j = 0; j < 4; j++) {                                 \
                    s1[j] = fmaf(W11[k], w[k + j].x, s1[j]);                  \
                    s2[j] = fmaf(W11[k], w[k + j].y, s2[j]);                  \
                }                                                             \
            }                                                                 \
            _Pragma("unroll")                                                 \
            for (int j = 0; j < 4; j++) pm[o + j] = make_float2(s1[j], s2[j]);\
        }                                                                     \
        _Pragma("unroll")                                                     \
        for (int t = 0; t < 14; t++) {                                        \
            float gv = w[t].x;                                                \
            float rv = w[t].y;                                                \
            w[t] = make_float2(fmaf(gv, gv, rv * rv), gv * rv);               \
        }                                                                     \
        {                                                                     \
            float s3[4] = {0.f, 0.f, 0.f, 0.f};                               \
            float s4[4] = {0.f, 0.f, 0.f, 0.f};                               \
            _Pragma("unroll")                                                 \
            for (int k = 0; k < 11; k++) {                                    \
                _Pragma("unroll")                                             \
                for (int j = 0; j < 4; j++) {                                 \
                    s3[j] = fmaf(W11[k], w[k + j].x, s3[j]);                  \
                    s4[j] = fmaf(W11[k], w[k + j].y, s4[j]);                  \
                }                                                             \
            }                                                                 \
            _Pragma("unroll")                                                 \
            for (int j = 0; j < 4; j++) pv[o + j] = make_float2(s3[j], s4[j]);\
        }                                                                     \
    }

    for (int i = start; i < end; i++) {
        const int ty = i & (NBY - 1);
        const int tx = (i >> 4) & (NBX - 1);
        const int tz = i >> 8;
        const int x0 = tx * TW;
        const int y0 = ty * TH;
        const size_t pb = (size_t)tz * (size_t)(H_IMG * W_IMG);
        const float* gp = gen + pb;
        const float* rp = ref + pb;
        const bool xin = (x0 >= 5) && (x0 + IW - 5 <= W_IMG);
        const bool reuse = (i > start) && (ty != 0);

        // ---- Phase A: (shift carried hconv rows) + stage input rows ----
        if (reuse) {
            if (tid < 320) {           // 10 rows x 32 cols: pm/pv rows 32..41 -> 0..9
                int r = tid >> 5;
                int c = tid & 31;
                pm[r * MS2 + c] = pm[(r + 32) * MS2 + c];
                pv[r * MS2 + c] = pv[(r + 32) * MS2 + c];
            }
            STAGE(y0 + 5, 32)          // input rows for hconv rows 10..41
        } else {
            STAGE(y0 - 5, IH)          // full 42 rows
        }
        __syncthreads();

        // ---- Phase B: horizontal conv ----
        if (reuse) {
            // 32 rows x 8 chunks = 256 items, single balanced pass
            int ch = tid >> 5;
            int r = tid & 31;
            HCONV(r, r + 10, ch << 2)
        } else {
            // 42 rows x 8 chunks = 336 items, row-fastest map
            for (int item = tid; item < IH * 8; item += NT) {
                int ch = item / IH;
                int r = item - ch * IH;
                HCONV(r, r, ch << 2)
            }
        }
        __syncthreads();

        // ---- Phase C: vertical conv (4 rows/thread), streaming SSIM ----
        {
            const int c = lane;
            const int r0 = wrp << 2;

            float q[4], p[4];
            {
                float2 v[14];
#pragma unroll
                for (int t = 0; t < 14; t++) v[t] = pm[(r0 + t) * MS2 + c];
#pragma unroll
                for (int j = 0; j < 4; j++) {
                    float o1 = 0.f, o2 = 0.f;
#pragma unroll
                    for (int k = 0; k < 11; k++) {
                        o1 = fmaf(W11[k], v[j + k].x, o1);
                        o2 = fmaf(W11[k], v[j + k].y, o2);
                    }
                    q[j] = fmaf(o1, o1, o2 * o2);
                    p[j] = o1 * o2;
                }
            }
            {
                float2 v[14];
#pragma unroll
                for (int t = 0; t < 14; t++) v[t] = pv[(r0 + t) * MS2 + c];
#pragma unroll
                for (int j = 0; j < 4; j++) {
                    float oss = 0.f, ogr = 0.f;
#pragma unroll
                    for (int k = 0; k < 11; k++) {
                        oss = fmaf(W11[k], v[j + k].x, oss);
                        ogr = fmaf(W11[k], v[j + k].y, ogr);
                    }
                    float num = fmaf(2.f, p[j], C1F) * fmaf(2.f, ogr - p[j], C2F);
                    float den = (q[j] + C1F) * (oss - q[j] + C2F);
                    lsum += __fdividef(num, den);
                }
            }
        }
        __syncthreads();   // protects pm/pv (shift) and sgr (stage) of next tile
    }

#undef STAGE
#undef HCONV

    // ---- Block reduction (fp32), once per persistent block ----
#pragma unroll
    for (int off = 16; off > 0; off >>= 1)
        lsum += __shfl_xor_sync(0xffffffffu, lsum, off);
    if (lane == 0) wsum[wrp] = lsum;
    __syncthreads();

    if (tid == 0) {
        float s = 0.f;
#pragma unroll
        for (int i = 0; i < 8; i++) s += wsum[i];
        g_partials[b] = s;
        __threadfence();
        unsigned int t = atomicAdd(&g_count, 1u);
        is_last = (t == (unsigned)(NPERS - 1));
    }
    __syncthreads();

    // ---- Last block: deterministic final reduction ----
    if (is_last) {
        __threadfence();
        double acc = 0.0;
        for (int i = tid; i < NPERS; i += NT)
            acc += (double)g_partials[i];
#pragma unroll
        for (int off = 16; off > 0; off >>= 1)
            acc += __shfl_xor_sync(0xffffffffu, acc, off);
        if (lane == 0) dsum[wrp] = acc;
        __syncthreads();
        if (tid == 0) {
            double s = 0.0;
#pragma unroll
            for (int i = 0; i < 8; i++) s += dsum[i];
            out[0] = (float)(1.0 - s / NPIX);
            g_count = 0;   // self-reset -> graph-replay deterministic
        }
    }
}

extern "C" void kernel_launch(void* const* d_in, const int* in_sizes, int n_in,
                              void* d_out, int out_size) {
    const float* gen = (const float*)d_in[0];
    const float* ref = (const float*)d_in[1];
    float* out = (float*)d_out;

    ssim_main<<<NPERS, NT>>>(gen, ref, out);
}

// round 16
// speedup vs baseline: 1.1910x; 1.1910x over previous
#include <cuda_runtime.h>

#define H_IMG 512
#define W_IMG 512
#define NPLANES 96            // 32 * 3
#define TW 32
#define TH 32
#define IW 42                 // TW + 10
#define IH 42                 // TH + 10
#define SS2 43                // staged (g,r) float2 stride
#define MS4 33                // intermediate float4 stride (odd -> LDS.128 conflict-free)
#define NT 256
#define NBX 16
#define NBY 16
#define NTILES (NBX * NBY * NPLANES)   // 24576
#define NPERS 740             // 148 SMs x 5 resident CTAs
#define C1F 6.5025f
#define C2F 58.5225f
#define NPIX 25165824.0       // 32*3*512*512

__device__ float g_partials[NPERS];
__device__ unsigned int g_count = 0;

#define W11_INIT {0.00102838f, 0.00759871f, 0.03600077f, 0.10936070f, \
                  0.21300560f, 0.26601180f, 0.21300560f, 0.10936070f, \
                  0.03600077f, 0.00759871f, 0.00102838f}

__global__ void __launch_bounds__(NT, 5) ssim_main(const float* __restrict__ gen,
                                                   const float* __restrict__ ref,
                                                   float* __restrict__ out) {
    __shared__ float2 sgr[IH * SS2];   // staged (g, r), scaled
    __shared__ float4 pq[IH * MS4];    // (conv_h g, conv_h r, conv_h g^2+r^2, conv_h g*r)
    __shared__ float wsum[8];
    __shared__ double dsum[8];
    __shared__ bool is_last;

    const float W11[11] = W11_INIT;    // compile-time consts -> FFMA-imm

    const int tid = threadIdx.x;
    const int lane = tid & 31;
    const int wrp = tid >> 5;
    const int bid = blockIdx.x;

    float lsum = 0.f;                  // accumulated across all tiles of this block

    for (int tile = bid; tile < NTILES; tile += NPERS) {
        // tile decode: all power-of-2 -> shifts
        const int bx = tile & (NBX - 1);
        const int by = (tile >> 4) & (NBY - 1);
        const int bz = tile >> 8;
        const int x0 = bx * TW;
        const int y0 = by * TH;
        const size_t pb = (size_t)bz * (size_t)(H_IMG * W_IMG);
        const float* gp = gen + pb;
        const float* rp = ref + pb;

        // ---- Stage 0: warp-per-row coalesced load, scale, pack, zero-pad ----
        const bool interior = (x0 >= 5) & (x0 + IW - 5 <= W_IMG) &
                              (y0 >= 5) & (y0 + IH - 5 <= H_IMG);
        if (interior) {
            const float* gb = gp + (long)(y0 - 5) * W_IMG + (x0 - 5);
            const float* rb = rp + (long)(y0 - 5) * W_IMG + (x0 - 5);
#pragma unroll
            for (int r = wrp; r < IH; r += 8) {
                const float* grow = gb + (long)r * W_IMG;
                const float* rrow = rb + (long)r * W_IMG;
                float2* srow = sgr + r * SS2;
                srow[lane] = make_float2(fmaf(grow[lane], 0.5f, 0.5f),
                                         fmaf(rrow[lane], 0.5f, 0.5f));
                if (lane < IW - 32)
                    srow[lane + 32] = make_float2(fmaf(grow[lane + 32], 0.5f, 0.5f),
                                                  fmaf(rrow[lane + 32], 0.5f, 0.5f));
            }
        } else {
#pragma unroll
            for (int r = wrp; r < IH; r += 8) {
                int gy = y0 + r - 5;
                bool rowok = (unsigned)gy < (unsigned)H_IMG;
                const float* grow = gp + (long)gy * W_IMG;
                const float* rrow = rp + (long)gy * W_IMG;
                float2* srow = sgr + r * SS2;
#pragma unroll
                for (int h = 0; h < 2; h++) {
                    int c = lane + h * 32;
                    if (c < IW) {
                        int gx = x0 + c - 5;
                        bool ok = rowok && ((unsigned)gx < (unsigned)W_IMG);
                        srow[c] = ok ? make_float2(fmaf(grow[gx], 0.5f, 0.5f),
                                                   fmaf(rrow[gx], 0.5f, 0.5f))
                                     : make_float2(0.f, 0.f);
                    }
                }
            }
        }
        __syncthreads();   // also orders prior tile's stage-2 reads before stage-1 writes

        // ---- Stage 1: horizontal conv, row-fastest map; halves stored as STS.64 ----
        for (int item = tid; item < IH * 8; item += NT) {
            int ch = item / IH;
            int r = item - ch * IH;
            int c0 = ch << 2;
            const float2* srow = sgr + r * SS2 + c0;
            float2* orow = reinterpret_cast<float2*>(pq + r * MS4 + c0);

            float2 w[14];
#pragma unroll
            for (int t = 0; t < 14; t++) w[t] = srow[t];

            // first moments (g, r) -> lo half of float4
            {
                float s1[4] = {0.f, 0.f, 0.f, 0.f};
                float s2[4] = {0.f, 0.f, 0.f, 0.f};
#pragma unroll
                for (int k = 0; k < 11; k++) {
#pragma unroll
                    for (int j = 0; j < 4; j++) {
                        s1[j] = fmaf(W11[k], w[k + j].x, s1[j]);
                        s2[j] = fmaf(W11[k], w[k + j].y, s2[j]);
                    }
                }
#pragma unroll
                for (int j = 0; j < 4; j++) orow[2 * j] = make_float2(s1[j], s2[j]);
            }

            // in-place transform: w <- (g^2 + r^2, g*r)
#pragma unroll
            for (int t = 0; t < 14; t++) {
                float gv = w[t].x;
                float rv = w[t].y;
                w[t] = make_float2(fmaf(gv, gv, rv * rv), gv * rv);
            }

            // second moments (ss, gr) -> hi half of float4
            {
                float s3[4] = {0.f, 0.f, 0.f, 0.f};
                float s4[4] = {0.f, 0.f, 0.f, 0.f};
#pragma unroll
                for (int k = 0; k < 11; k++) {
#pragma unroll
                    for (int j = 0; j < 4; j++) {
                        s3[j] = fmaf(W11[k], w[k + j].x, s3[j]);
                        s4[j] = fmaf(W11[k], w[k + j].y, s4[j]);
                    }
                }
#pragma unroll
                for (int j = 0; j < 4; j++) orow[2 * j + 1] = make_float2(s3[j], s4[j]);
            }
        }
        __syncthreads();

        // ---- Stage 2: streaming vertical conv (4 rows/thread, LDS.128) + SSIM ----
        {
            const int c = lane;
            const int r0 = wrp << 2;   // 8 warps * 4 rows = 32

            float am1[4] = {0.f, 0.f, 0.f, 0.f};
            float am2[4] = {0.f, 0.f, 0.f, 0.f};
            float ass[4] = {0.f, 0.f, 0.f, 0.f};
            float agr[4] = {0.f, 0.f, 0.f, 0.f};
#pragma unroll
            for (int t = 0; t < 14; t++) {
                float4 v = pq[(r0 + t) * MS4 + c];
#pragma unroll
                for (int j = 0; j < 4; j++) {
                    int k = t - j;
                    if (k >= 0 && k < 11) {
                        am1[j] = fmaf(W11[k], v.x, am1[j]);
                        am2[j] = fmaf(W11[k], v.y, am2[j]);
                        ass[j] = fmaf(W11[k], v.z, ass[j]);
                        agr[j] = fmaf(W11[k], v.w, agr[j]);
                    }
                }
            }
#pragma unroll
            for (int j = 0; j < 4; j++) {
                float o1 = am1[j], o2 = am2[j];
                float q = fmaf(o1, o1, o2 * o2);
                float p = o1 * o2;
                float num = fmaf(2.f, p, C1F) * fmaf(2.f, agr[j] - p, C2F);
                float den = (q + C1F) * (ass[j] - q + C2F);
                lsum += __fdividef(num, den);
            }
        }
    }

    // ---- Block reduction (fp32), once per persistent block ----
#pragma unroll
    for (int off = 16; off > 0; off >>= 1)
        lsum += __shfl_xor_sync(0xffffffffu, lsum, off);
    if (lane == 0) wsum[wrp] = lsum;
    __syncthreads();

    if (tid == 0) {
        float s = 0.f;
#pragma unroll
        for (int i = 0; i < 8; i++) s += wsum[i];
        g_partials[bid] = s;
        __threadfence();
        unsigned int t = atomicAdd(&g_count, 1u);
        is_last = (t == (unsigned)(NPERS - 1));
    }
    __syncthreads();

    // ---- Last block: deterministic final reduction ----
    if (is_last) {
        __threadfence();
        double acc = 0.0;
        for (int i = tid; i < NPERS; i += NT)
            acc += (double)g_partials[i];
#pragma unroll
        for (int off = 16; off > 0; off >>= 1)
            acc += __shfl_xor_sync(0xffffffffu, acc, off);
        if (lane == 0) dsum[wrp] = acc;
        __syncthreads();
        if (tid == 0) {
            double s = 0.0;
#pragma unroll
            for (int i = 0; i < 8; i++) s += dsum[i];
            out[0] = (float)(1.0 - s / NPIX);
            g_count = 0;   // self-reset -> graph-replay deterministic
        }
    }
}

extern "C" void kernel_launch(void* const* d_in, const int* in_sizes, int n_in,
                              void* d_out, int out_size) {
    const float* gen = (const float*)d_in[0];
    const float* ref = (const float*)d_in[1];
    float* out = (float*)d_out;

    ssim_main<<<NPERS, NT>>>(gen, ref, out);
}